// round 1
// baseline (speedup 1.0000x reference)
#include <cuda_runtime.h>

#define FN 128
#define FE 64
#define KN 32
#define NMAX 50000

// Scratch (static device allocations are the sanctioned workaround)
__device__ float g_wcomb[FN * 192];        // [128][192] = [wqk(64) | wv(128)]
__device__ float g_qk[NMAX * FE];          // [N][64]
__device__ float g_nodesV[NMAX * FN];      // [N][128]

// ---------------------------------------------------------------------------
// K0: wcomb[f][j] = (j<64) ? sum_t wq[f][t]*wk[j][t]   (= wq @ wk^T)
//                         : wv[f][j-64]
// ---------------------------------------------------------------------------
__global__ void k0_weights(const float* __restrict__ wq,
                           const float* __restrict__ wk,
                           const float* __restrict__ wv) {
    int idx = blockIdx.x * blockDim.x + threadIdx.x;
    if (idx >= FN * 192) return;
    int f = idx / 192, j = idx % 192;
    float acc;
    if (j < FE) {
        acc = 0.f;
        #pragma unroll 8
        for (int t = 0; t < FE; t++) acc += wq[f * FE + t] * wk[j * FE + t];
    } else {
        acc = wv[f * FN + (j - FE)];
    }
    g_wcomb[idx] = acc;
}

// ---------------------------------------------------------------------------
// K1: C[N,192] = nodes[N,128] @ wcomb[128,192]; columns 0..63 -> g_qk,
// columns 64..191 -> g_nodesV. Tiled 64x64 per block (blockIdx.y = col panel).
// ---------------------------------------------------------------------------
__global__ __launch_bounds__(256) void k1_gemm(const float* __restrict__ nodes, int N) {
    __shared__ __align__(16) float As[64 * 132];   // [64][132] padded rows
    __shared__ __align__(16) float Bs[128 * 64];   // [128][64]

    int tid  = threadIdx.x;
    int row0 = blockIdx.x * 64;
    int panel = blockIdx.y;                        // 0: qk, 1: V[0:64], 2: V[64:128]

    // Load A tile: 64 rows x 128 k, float4 coalesced
    const float4* nodes4 = (const float4*)nodes;
    #pragma unroll
    for (int c = 0; c < 8; c++) {
        int idx = tid + c * 256;                   // 0..2047 float4s
        int r  = idx >> 5;                         // 0..63
        int k4 = idx & 31;                         // 0..31
        int row = row0 + r;
        float4 v = (row < N) ? nodes4[(size_t)row * 32 + k4]
                             : make_float4(0.f, 0.f, 0.f, 0.f);
        ((float4*)(As + r * 132))[k4] = v;         // 132*4 % 16 == 0, aligned
    }
    // Load B panel: 128 rows x 64 cols of the 192-wide wcomb
    const float4* B4 = (const float4*)g_wcomb;     // row stride 48 float4
    #pragma unroll
    for (int c = 0; c < 8; c++) {
        int idx = tid + c * 256;                   // 0..2047 float4s
        int k  = idx >> 4;                         // 0..127
        int j4 = idx & 15;                         // 0..15
        ((float4*)(Bs + k * 64))[j4] = B4[k * 48 + panel * 16 + j4];
    }
    __syncthreads();

    int tx = tid & 15;                             // col group (x4)
    int ty = tid >> 4;                             // row group (x4)
    float acc[4][4] = {};

    #pragma unroll 4
    for (int k = 0; k < 128; k++) {
        float4 b = ((const float4*)(Bs + k * 64))[tx];
        float a0 = As[(ty * 4 + 0) * 132 + k];
        float a1 = As[(ty * 4 + 1) * 132 + k];
        float a2 = As[(ty * 4 + 2) * 132 + k];
        float a3 = As[(ty * 4 + 3) * 132 + k];
        acc[0][0] += a0 * b.x; acc[0][1] += a0 * b.y; acc[0][2] += a0 * b.z; acc[0][3] += a0 * b.w;
        acc[1][0] += a1 * b.x; acc[1][1] += a1 * b.y; acc[1][2] += a1 * b.z; acc[1][3] += a1 * b.w;
        acc[2][0] += a2 * b.x; acc[2][1] += a2 * b.y; acc[2][2] += a2 * b.z; acc[2][3] += a2 * b.w;
        acc[3][0] += a3 * b.x; acc[3][1] += a3 * b.y; acc[3][2] += a3 * b.z; acc[3][3] += a3 * b.w;
    }

    #pragma unroll
    for (int i = 0; i < 4; i++) {
        int row = row0 + ty * 4 + i;
        if (row >= N) continue;
        float4 o = make_float4(acc[i][0], acc[i][1], acc[i][2], acc[i][3]);
        if (panel == 0) {
            ((float4*)g_qk)[(size_t)row * 16 + tx] = o;
        } else {
            ((float4*)g_nodesV)[(size_t)row * 32 + (panel - 1) * 16 + tx] = o;
        }
    }
}

// ---------------------------------------------------------------------------
// K2: per node (one 128-thread block): logits = inv_deg * edges[n] . qk[n],
// softmax over K=32, out[n] = sum_k b[k] * nodesV[nlist[n,k]]
// ---------------------------------------------------------------------------
__global__ __launch_bounds__(128) void k2_fused(const float* __restrict__ edges,
                                                const int*   __restrict__ nlist,
                                                const float* __restrict__ invdeg,
                                                float*       __restrict__ out,
                                                int N) {
    int n = blockIdx.x;
    int tid = threadIdx.x;

    __shared__ __align__(16) float qk_s[64];
    __shared__ float logits[32];
    __shared__ float b_s[32];
    __shared__ int   idx_s[32];

    if (tid < 64) {
        qk_s[tid] = g_qk[(size_t)n * 64 + tid];
    } else if (tid < 96) {
        idx_s[tid - 64] = nlist[(size_t)n * KN + (tid - 64)];
    }
    __syncthreads();

    // ---- logits: thread handles (k = tid/4, quarter = tid%4 of the 64-dot) ----
    int k    = tid >> 2;
    int part = tid & 3;
    const float4* e4 = (const float4*)edges + (size_t)n * 512 + k * 16 + part * 4;
    const float4* q4 = (const float4*)qk_s + part * 4;

    float4 v0 = e4[0], v1 = e4[1], v2 = e4[2], v3 = e4[3];
    float4 q0 = q4[0], q1 = q4[1], q2 = q4[2], q3 = q4[3];
    float s = v0.x * q0.x + v0.y * q0.y + v0.z * q0.z + v0.w * q0.w;
    s      += v1.x * q1.x + v1.y * q1.y + v1.z * q1.z + v1.w * q1.w;
    s      += v2.x * q2.x + v2.y * q2.y + v2.z * q2.z + v2.w * q2.w;
    s      += v3.x * q3.x + v3.y * q3.y + v3.z * q3.z + v3.w * q3.w;
    s += __shfl_xor_sync(0xffffffffu, s, 1);
    s += __shfl_xor_sync(0xffffffffu, s, 2);
    if (part == 0) logits[k] = s;
    __syncthreads();

    // ---- softmax over 32 (warp 0) ----
    if (tid < 32) {
        float v = logits[tid] * invdeg[n];
        float m = v;
        #pragma unroll
        for (int o = 16; o; o >>= 1) m = fmaxf(m, __shfl_xor_sync(0xffffffffu, m, o));
        float e = __expf(v - m);
        float sum = e;
        #pragma unroll
        for (int o = 16; o; o >>= 1) sum += __shfl_xor_sync(0xffffffffu, sum, o);
        b_s[tid] = e / sum;
    }
    __syncthreads();

    // ---- weighted gather of nodesV rows (L2-resident, 25.6 MB) ----
    float acc = 0.f;
    #pragma unroll
    for (int kk = 0; kk < KN; kk++) {
        acc += b_s[kk] * g_nodesV[(size_t)idx_s[kk] * FN + tid];
    }
    out[(size_t)n * FN + tid] = acc;
}

// ---------------------------------------------------------------------------
extern "C" void kernel_launch(void* const* d_in, const int* in_sizes, int n_in,
                              void* d_out, int out_size) {
    const float* nodes  = (const float*)d_in[0];
    const int*   nlist  = (const int*)  d_in[1];
    const float* edges  = (const float*)d_in[2];
    const float* invdeg = (const float*)d_in[3];
    const float* wq     = (const float*)d_in[4];
    const float* wk     = (const float*)d_in[5];
    const float* wv     = (const float*)d_in[6];
    float* out = (float*)d_out;
    int N = in_sizes[3];                           // inv_degree element count

    k0_weights<<<(FN * 192 + 255) / 256, 256>>>(wq, wk, wv);
    dim3 g1((N + 63) / 64, 3);
    k1_gemm<<<g1, 256>>>(nodes, N);
    k2_fused<<<N, 128>>>(edges, nlist, invdeg, out, N);
}